// round 15
// baseline (speedup 1.0000x reference)
#include <cuda_runtime.h>
#include <mma.h>

using namespace nvcuda;

#define NN 10000
#define NE 320000
#define DH 256
#define NC 40

// Static scratch (allowed): 5 rotating feature buffers + weight splits + CSR.
__device__ __align__(16) float4 g_buf0[NN * DH / 4];
__device__ __align__(16) float4 g_buf1[NN * DH / 4];
__device__ __align__(16) float4 g_buf2[NN * DH / 4];
__device__ __align__(16) float4 g_buf3[NN * DH / 4];
__device__ __align__(16) float4 g_buf4[NN * DH / 4];
__device__ __align__(16) float g_wh1[DH * DH];
__device__ __align__(16) float g_wl1[DH * DH];
__device__ __align__(16) float g_wh2[DH * DH];
__device__ __align__(16) float g_wl2[DH * DH];
__device__ int g_idx[2 * NE];
__device__ int g_deg[NN];
__device__ int g_off[NN + 1];
__device__ int g_cur[NN];
__device__ int g_esrc[NE];
__device__ int g_is64;

// ---------------------------------------------------------------------------
// CSR build chain (unchanged).
// ---------------------------------------------------------------------------
__global__ void detect_and_zero(const int* __restrict__ p)
{
    const int i = blockIdx.x * blockDim.x + threadIdx.x;
    if (i < NN) g_deg[i] = 0;
    if (i == 0) {
        int any_nonzero = 0;
        for (int k = 0; k < 64; k++)
            any_nonzero |= p[2 * k + 1];
        g_is64 = (any_nonzero == 0) ? 1 : 0;
    }
}

__global__ void convert_hist(const void* __restrict__ p)
{
    const int i = blockIdx.x * blockDim.x + threadIdx.x;
    if (i >= 2 * NE) return;
    int v;
    if (g_is64) v = (int)((const long long*)p)[i];
    else        v = ((const int*)p)[i];
    v = min(max(v, 0), NN - 1);
    g_idx[i] = v;
    if (i >= NE) atomicAdd(&g_deg[v], 1);
}

__global__ void scan_deg_fast()
{
    const int t = threadIdx.x;
    const int lane = t & 31, warp = t >> 5;
    const int base = t * 10;

    int lexcl[10];
    int sum = 0;
#pragma unroll
    for (int i = 0; i < 10; i++) {
        const int idx = base + i;
        const int v = (idx < NN) ? __ldg(&g_deg[idx]) : 0;
        lexcl[i] = sum;
        sum += v;
    }

    int x = sum;
#pragma unroll
    for (int d = 1; d < 32; d <<= 1) {
        int y = __shfl_up_sync(0xffffffffu, x, d);
        if (lane >= d) x += y;
    }
    __shared__ int wsum[32];
    if (lane == 31) wsum[warp] = x;
    __syncthreads();
    if (warp == 0) {
        int w = wsum[lane];
#pragma unroll
        for (int d = 1; d < 32; d <<= 1) {
            int y = __shfl_up_sync(0xffffffffu, w, d);
            if (lane >= d) w += y;
        }
        wsum[lane] = w;
    }
    __syncthreads();

    const int texcl = (x - sum) + (warp ? wsum[warp - 1] : 0);
#pragma unroll
    for (int i = 0; i < 10; i++) {
        const int idx = base + i;
        if (idx < NN) {
            const int o = texcl + lexcl[i];
            g_off[idx] = o;
            g_cur[idx] = o;
        }
    }
    if (t == 1023) g_off[NN] = wsum[31];
}

__global__ void fill_csr()
{
    const int e = blockIdx.x * blockDim.x + threadIdx.x;
    if (e >= NE) return;
    const int dst = g_idx[NE + e];
    const int pos = atomicAdd(&g_cur[dst], 1);
    g_esrc[pos] = g_idx[e];
}

// ---------------------------------------------------------------------------
// Elementwise tf32 split: v = hi + lo, both tf32-representable.
// ---------------------------------------------------------------------------
__global__ void split2(const float4* __restrict__ in, float4* __restrict__ h,
                       float4* __restrict__ l, int n4)
{
    const int i = blockIdx.x * blockDim.x + threadIdx.x;
    if (i >= n4) return;
    const float4 v = in[i];
    float4 hv, lv;
    hv.x = wmma::__float_to_tf32(v.x); lv.x = wmma::__float_to_tf32(v.x - hv.x);
    hv.y = wmma::__float_to_tf32(v.y); lv.y = wmma::__float_to_tf32(v.y - hv.y);
    hv.z = wmma::__float_to_tf32(v.z); lv.z = wmma::__float_to_tf32(v.z - hv.z);
    hv.w = wmma::__float_to_tf32(v.w); lv.w = wmma::__float_to_tf32(v.w - hv.w);
    h[i] = hv; l[i] = lv;
}

// ---------------------------------------------------------------------------
// 3xTF32 tensor-core GEMM, preconverted operands, NO bias:
// C[M,256] = (Ah+Al)[M,256] @ (Bh+Bl)[256,256]  (3-term: AhBh + AhBl + AlBh)
// 128x64 block tile, 8 warps (4M x 2N), warp 32x32 = 2x2 m16n16k8, BK=16.
// ---------------------------------------------------------------------------
#define AS 20   // smem stride for A tiles [m][k], floats
#define BS 72   // smem stride for B tiles [k][n], floats

__global__ void __launch_bounds__(256)
gemm3tf32(const float* __restrict__ Ah, const float* __restrict__ Al,
          const float* __restrict__ Bh, const float* __restrict__ Bl,
          float* __restrict__ C, int M)
{
    constexpr int KD = 256, ND = 256, BK = 16;
    __shared__ __align__(16) float sAh[128 * AS];
    __shared__ __align__(16) float sAl[128 * AS];
    __shared__ __align__(16) float sBh[BK * BS];
    __shared__ __align__(16) float sBl[BK * BS];

    const int tid = threadIdx.x;
    const int wid = tid >> 5;
    const int wm = wid & 3, wn = wid >> 2;
    const int m0 = blockIdx.y * 128;
    const int n0 = blockIdx.x * 64;

    using FragA = wmma::fragment<wmma::matrix_a, 16, 16, 8, wmma::precision::tf32, wmma::row_major>;
    using FragB = wmma::fragment<wmma::matrix_b, 16, 16, 8, wmma::precision::tf32, wmma::row_major>;
    using FragC = wmma::fragment<wmma::accumulator, 16, 16, 8, float>;

    FragC acc[2][2];
#pragma unroll
    for (int i = 0; i < 2; i++)
#pragma unroll
        for (int j = 0; j < 2; j++) wmma::fill_fragment(acc[i][j], 0.f);

    // A tile: 128x16 = 512 float4 -> 2/thread each for Ah, Al.
    // B tile: 16x64  = 256 float4 -> 1/thread each for Bh, Bl.
    const int a_r0 = (tid + 0)   >> 2, a_c0 = (tid + 0)   & 3;
    const int a_r1 = (tid + 256) >> 2, a_c1 = (tid + 256) & 3;
    const int b_r  = tid >> 4,         b_c  = tid & 15;

    const float4 z4 = make_float4(0.f, 0.f, 0.f, 0.f);
    float4 rah0, rah1, ral0, ral1, rbh, rbl;

    {
        const bool ok0 = (m0 + a_r0) < M, ok1 = (m0 + a_r1) < M;
        rah0 = ok0 ? *reinterpret_cast<const float4*>(&Ah[(size_t)(m0 + a_r0) * KD + a_c0 * 4]) : z4;
        ral0 = ok0 ? *reinterpret_cast<const float4*>(&Al[(size_t)(m0 + a_r0) * KD + a_c0 * 4]) : z4;
        rah1 = ok1 ? *reinterpret_cast<const float4*>(&Ah[(size_t)(m0 + a_r1) * KD + a_c1 * 4]) : z4;
        ral1 = ok1 ? *reinterpret_cast<const float4*>(&Al[(size_t)(m0 + a_r1) * KD + a_c1 * 4]) : z4;
        rbh  = *reinterpret_cast<const float4*>(&Bh[(size_t)b_r * ND + n0 + b_c * 4]);
        rbl  = *reinterpret_cast<const float4*>(&Bl[(size_t)b_r * ND + n0 + b_c * 4]);
    }

    for (int s = 0; s < KD / BK; s++) {
        *reinterpret_cast<float4*>(&sAh[a_r0 * AS + a_c0 * 4]) = rah0;
        *reinterpret_cast<float4*>(&sAh[a_r1 * AS + a_c1 * 4]) = rah1;
        *reinterpret_cast<float4*>(&sAl[a_r0 * AS + a_c0 * 4]) = ral0;
        *reinterpret_cast<float4*>(&sAl[a_r1 * AS + a_c1 * 4]) = ral1;
        *reinterpret_cast<float4*>(&sBh[b_r * BS + b_c * 4]) = rbh;
        *reinterpret_cast<float4*>(&sBl[b_r * BS + b_c * 4]) = rbl;
        __syncthreads();

        if (s + 1 < KD / BK) {
            const int k0 = (s + 1) * BK;
            const bool ok0 = (m0 + a_r0) < M, ok1 = (m0 + a_r1) < M;
            rah0 = ok0 ? *reinterpret_cast<const float4*>(&Ah[(size_t)(m0 + a_r0) * KD + k0 + a_c0 * 4]) : z4;
            ral0 = ok0 ? *reinterpret_cast<const float4*>(&Al[(size_t)(m0 + a_r0) * KD + k0 + a_c0 * 4]) : z4;
            rah1 = ok1 ? *reinterpret_cast<const float4*>(&Ah[(size_t)(m0 + a_r1) * KD + k0 + a_c1 * 4]) : z4;
            ral1 = ok1 ? *reinterpret_cast<const float4*>(&Al[(size_t)(m0 + a_r1) * KD + k0 + a_c1 * 4]) : z4;
            rbh  = *reinterpret_cast<const float4*>(&Bh[(size_t)(k0 + b_r) * ND + n0 + b_c * 4]);
            rbl  = *reinterpret_cast<const float4*>(&Bl[(size_t)(k0 + b_r) * ND + n0 + b_c * 4]);
        }

#pragma unroll
        for (int k8 = 0; k8 < BK; k8 += 8) {
            FragA fah[2], fal[2];
            FragB fbh[2], fbl[2];
#pragma unroll
            for (int mi = 0; mi < 2; mi++) {
                wmma::load_matrix_sync(fah[mi], &sAh[(wm * 32 + mi * 16) * AS + k8], AS);
                wmma::load_matrix_sync(fal[mi], &sAl[(wm * 32 + mi * 16) * AS + k8], AS);
            }
#pragma unroll
            for (int ni = 0; ni < 2; ni++) {
                wmma::load_matrix_sync(fbh[ni], &sBh[k8 * BS + wn * 32 + ni * 16], BS);
                wmma::load_matrix_sync(fbl[ni], &sBl[k8 * BS + wn * 32 + ni * 16], BS);
            }
#pragma unroll
            for (int mi = 0; mi < 2; mi++)
#pragma unroll
                for (int ni = 0; ni < 2; ni++) {
                    wmma::mma_sync(acc[mi][ni], fah[mi], fbl[ni], acc[mi][ni]);
                    wmma::mma_sync(acc[mi][ni], fal[mi], fbh[ni], acc[mi][ni]);
                    wmma::mma_sync(acc[mi][ni], fah[mi], fbh[ni], acc[mi][ni]);
                }
        }
        __syncthreads();
    }

    // Direct store (M is a multiple of 16 -> tiles fully in or out).
#pragma unroll
    for (int mi = 0; mi < 2; mi++) {
        const int row = m0 + wm * 32 + mi * 16;
        if (row + 16 > M) continue;
#pragma unroll
        for (int ni = 0; ni < 2; ni++)
            wmma::store_matrix_sync(&C[(size_t)row * ND + n0 + wn * 32 + ni * 16],
                                    acc[mi][ni], ND, wmma::mem_row_major);
    }
}

// ---------------------------------------------------------------------------
// Tiled SGEMM 64x64, layer 3: C = (Ah+Al) @ B  (no bias, no relu).
// ---------------------------------------------------------------------------
__global__ void gemm64s(const float* __restrict__ Ah, const float* __restrict__ Al,
                        const float* __restrict__ B, float* __restrict__ C,
                        int M, int N, int K)
{
    __shared__ float As[16][64];
    __shared__ float Bs[16][64];
    const int tid = threadIdx.x;
    const int ty = tid >> 4, tx = tid & 15;
    const int m0 = blockIdx.y * 64;
    const int n0 = blockIdx.x * 64;

    float acc[4][4];
#pragma unroll
    for (int i = 0; i < 4; i++)
#pragma unroll
        for (int j = 0; j < 4; j++) acc[i][j] = 0.f;

    const int la = tid * 4;
    const int ar = la >> 4, ac = la & 15;
    const int br = la >> 6, bc = la & 63;
    const int grow = m0 + ar;
    const int gcol = n0 + bc;

    const float4 z4 = make_float4(0.f, 0.f, 0.f, 0.f);
    float4 vah = z4, val = z4;
    if (grow < M) {
        vah = *reinterpret_cast<const float4*>(&Ah[(size_t)grow * K + ac]);
        val = *reinterpret_cast<const float4*>(&Al[(size_t)grow * K + ac]);
    }
    float4 vb = z4;
    if (gcol < N)
        vb = *reinterpret_cast<const float4*>(&B[(size_t)br * N + gcol]);

    for (int k0 = 0; k0 < K; k0 += 16) {
        As[ac + 0][ar] = vah.x + val.x; As[ac + 1][ar] = vah.y + val.y;
        As[ac + 2][ar] = vah.z + val.z; As[ac + 3][ar] = vah.w + val.w;
        Bs[br][bc + 0] = vb.x; Bs[br][bc + 1] = vb.y;
        Bs[br][bc + 2] = vb.z; Bs[br][bc + 3] = vb.w;
        __syncthreads();

        if (k0 + 16 < K) {
            vah = z4; val = z4;
            if (grow < M) {
                vah = *reinterpret_cast<const float4*>(&Ah[(size_t)grow * K + k0 + 16 + ac]);
                val = *reinterpret_cast<const float4*>(&Al[(size_t)grow * K + k0 + 16 + ac]);
            }
            vb = z4;
            if (gcol < N)
                vb = *reinterpret_cast<const float4*>(&B[(size_t)(k0 + 16 + br) * N + gcol]);
        }

#pragma unroll
        for (int k = 0; k < 16; k++) {
            const float4 a4 = *reinterpret_cast<const float4*>(&As[k][ty * 4]);
            const float4 b4 = *reinterpret_cast<const float4*>(&Bs[k][tx * 4]);
            const float a[4] = {a4.x, a4.y, a4.z, a4.w};
            const float b[4] = {b4.x, b4.y, b4.z, b4.w};
#pragma unroll
            for (int i = 0; i < 4; i++)
#pragma unroll
                for (int j = 0; j < 4; j++)
                    acc[i][j] += a[i] * b[j];
        }
        __syncthreads();
    }

#pragma unroll
    for (int i = 0; i < 4; i++) {
        int row = m0 + ty * 4 + i;
        if (row >= M) continue;
#pragma unroll
        for (int j = 0; j < 4; j++) {
            int col = n0 + tx * 4 + j;
            if (col < N)
                C[(size_t)row * N + col] = acc[i][j];
        }
    }
}

// ---------------------------------------------------------------------------
// Pull-mode aggregation D=256 + bias-fold (deg*b) + ReLU + tf32 split.
// out = relu(sum_src msg + deg*bias) -> (hi, lo).
// ---------------------------------------------------------------------------
__global__ void agg_split(const float4* __restrict__ h4,
                          const float4* __restrict__ bias4,
                          float4* __restrict__ outh, float4* __restrict__ outl)
{
    const int tid = threadIdx.x;
    const int node = blockIdx.x * 4 + (tid >> 6);
    const int f4 = tid & 63;
    if (node >= NN) return;
    const int beg = g_off[node], end = g_off[node + 1];

    float4 acc = make_float4(0.f, 0.f, 0.f, 0.f);
    int e = beg;
    for (; e + 4 <= end; e += 4) {
        const int s0 = g_esrc[e + 0], s1 = g_esrc[e + 1];
        const int s2 = g_esrc[e + 2], s3 = g_esrc[e + 3];
        const float4 v0 = h4[(size_t)s0 * 64 + f4];
        const float4 v1 = h4[(size_t)s1 * 64 + f4];
        const float4 v2 = h4[(size_t)s2 * 64 + f4];
        const float4 v3 = h4[(size_t)s3 * 64 + f4];
        acc.x += (v0.x + v1.x) + (v2.x + v3.x);
        acc.y += (v0.y + v1.y) + (v2.y + v3.y);
        acc.z += (v0.z + v1.z) + (v2.z + v3.z);
        acc.w += (v0.w + v1.w) + (v2.w + v3.w);
    }
    for (; e < end; e++) {
        const float4 v = h4[(size_t)g_esrc[e] * 64 + f4];
        acc.x += v.x; acc.y += v.y; acc.z += v.z; acc.w += v.w;
    }

    const float d = (float)(end - beg);
    const float4 b = bias4[f4];
    const float vx = fmaxf(fmaf(d, b.x, acc.x), 0.f);
    const float vy = fmaxf(fmaf(d, b.y, acc.y), 0.f);
    const float vz = fmaxf(fmaf(d, b.z, acc.z), 0.f);
    const float vw = fmaxf(fmaf(d, b.w, acc.w), 0.f);

    float4 hv, lv;
    hv.x = wmma::__float_to_tf32(vx); lv.x = wmma::__float_to_tf32(vx - hv.x);
    hv.y = wmma::__float_to_tf32(vy); lv.y = wmma::__float_to_tf32(vy - hv.y);
    hv.z = wmma::__float_to_tf32(vz); lv.z = wmma::__float_to_tf32(vz - hv.z);
    hv.w = wmma::__float_to_tf32(vw); lv.w = wmma::__float_to_tf32(vw - hv.w);
    outh[(size_t)node * 64 + f4] = hv;
    outl[(size_t)node * 64 + f4] = lv;
}

// ---------------------------------------------------------------------------
// Final aggregation D=40: out = relu(sum_src msg + deg*bias).
// ---------------------------------------------------------------------------
__global__ void agg40_relu(const float* __restrict__ h, const float* __restrict__ bias,
                           float* __restrict__ out)
{
    const int tid = threadIdx.x;
    const int node = blockIdx.x * 8 + tid / NC;
    const int f = tid % NC;
    if (node >= NN) return;
    const int beg = g_off[node], end = g_off[node + 1];

    float acc = 0.f;
    int e = beg;
    for (; e + 4 <= end; e += 4) {
        const int s0 = g_esrc[e + 0], s1 = g_esrc[e + 1];
        const int s2 = g_esrc[e + 2], s3 = g_esrc[e + 3];
        const float v0 = h[(size_t)s0 * NC + f];
        const float v1 = h[(size_t)s1 * NC + f];
        const float v2 = h[(size_t)s2 * NC + f];
        const float v3 = h[(size_t)s3 * NC + f];
        acc += (v0 + v1) + (v2 + v3);
    }
    for (; e < end; e++)
        acc += h[(size_t)g_esrc[e] * NC + f];
    const float d = (float)(end - beg);
    out[(size_t)node * NC + f] = fmaxf(fmaf(d, bias[f], acc), 0.f);
}

// ---------------------------------------------------------------------------
extern "C" void kernel_launch(void* const* d_in, const int* in_sizes, int n_in,
                              void* d_out, int out_size)
{
    const float* x  = (const float*)d_in[0];
    const void*  ei = d_in[1];
    const float* W1 = (const float*)d_in[2];
    const float* b1 = (const float*)d_in[3];
    const float* W2 = (const float*)d_in[4];
    const float* b2 = (const float*)d_in[5];
    const float* W3 = (const float*)d_in[6];
    const float* b3 = (const float*)d_in[7];
    float* out = (float*)d_out;

    float4 *buf0, *buf1, *buf2, *buf3, *buf4;
    float *wh1, *wl1, *wh2, *wl2;
    cudaGetSymbolAddress((void**)&buf0, g_buf0);
    cudaGetSymbolAddress((void**)&buf1, g_buf1);
    cudaGetSymbolAddress((void**)&buf2, g_buf2);
    cudaGetSymbolAddress((void**)&buf3, g_buf3);
    cudaGetSymbolAddress((void**)&buf4, g_buf4);
    cudaGetSymbolAddress((void**)&wh1, g_wh1);
    cudaGetSymbolAddress((void**)&wl1, g_wl1);
    cudaGetSymbolAddress((void**)&wh2, g_wh2);
    cudaGetSymbolAddress((void**)&wl2, g_wl2);
    float* f0 = (float*)buf0;
    float* f1 = (float*)buf1;
    float* f2 = (float*)buf2;
    float* f3 = (float*)buf3;
    float* f4 = (float*)buf4;

    static cudaStream_t s_side = nullptr;
    static cudaEvent_t ev_fork = nullptr, ev_csr = nullptr;
    if (s_side == nullptr) {
        cudaStreamCreateWithFlags(&s_side, cudaStreamNonBlocking);
        cudaEventCreateWithFlags(&ev_fork, cudaEventDisableTiming);
        cudaEventCreateWithFlags(&ev_csr,  cudaEventDisableTiming);
    }

    const dim3 blk(256);
    const dim3 gTF(4, (NN + 127) / 128);             // (4, 79)
    const dim3 gCls((NC + 63) / 64, (NN + 63) / 64); // (1, 157)
    const int n4x = NN * DH / 4;                     // 640000
    const int n4w = DH * DH / 4;                     // 16384

    // ---- Fork: CSR build on side stream ----
    cudaEventRecord(ev_fork, 0);
    cudaStreamWaitEvent(s_side, ev_fork, 0);
    detect_and_zero<<<(NN + 255) / 256, blk, 0, s_side>>>((const int*)ei);
    convert_hist<<<(2 * NE + 255) / 256, blk, 0, s_side>>>(ei);
    scan_deg_fast<<<1, 1024, 0, s_side>>>();
    fill_csr<<<(NE + 255) / 256, blk, 0, s_side>>>();
    cudaEventRecord(ev_csr, s_side);

    // ---- Main: splits + layer-1 GEMM, overlapping CSR ----
    split2<<<(n4x + 255) / 256, blk>>>((const float4*)x, buf0, buf1, n4x);
    split2<<<(n4w + 255) / 256, blk>>>((const float4*)W1, (float4*)wh1, (float4*)wl1, n4w);
    split2<<<(n4w + 255) / 256, blk>>>((const float4*)W2, (float4*)wh2, (float4*)wl2, n4w);
    gemm3tf32<<<gTF, blk>>>(f0, f1, wh1, wl1, f2, NN);

    // ---- Join: aggregation needs CSR ----
    cudaStreamWaitEvent(0, ev_csr, 0);
    agg_split<<<(NN + 3) / 4, blk>>>(buf2, (const float4*)b1, buf3, buf4);

    // ---- Layer 2 ----
    gemm3tf32<<<gTF, blk>>>(f3, f4, wh2, wl2, f2, NN);
    agg_split<<<(NN + 3) / 4, blk>>>(buf2, (const float4*)b2, buf0, buf1);

    // ---- Layer 3 ----
    gemm64s<<<gCls, blk>>>(f0, f1, W3, f3, NN, NC, DH);
    agg40_relu<<<(NN + 7) / 8, 320>>>(f3, b3, out);
}

// round 16
// speedup vs baseline: 1.4409x; 1.4409x over previous
#include <cuda_runtime.h>

#define NN 10000
#define NE 320000
#define DH 256
#define NC 40

// Static scratch (allowed).
__device__ __align__(16) float4 g_bufA[NN * DH / 4];
__device__ __align__(16) float4 g_bufB[NN * DH / 4];
__device__ int g_idx[2 * NE];      // [0,NE)=src, [NE,2NE)=dst (clean int32)
__device__ int g_deg[NN];
__device__ int g_off[NN + 1];
__device__ int g_cur[NN];
__device__ int g_esrc[NE];         // src ids grouped by dst (CSR payload)
__device__ int g_is64;

// ---------------------------------------------------------------------------
// Detect edge-index dtype (int64 vs int32) AND zero the degree histogram.
// ---------------------------------------------------------------------------
__global__ void detect_and_zero(const int* __restrict__ p)
{
    const int i = blockIdx.x * blockDim.x + threadIdx.x;
    if (i < NN) g_deg[i] = 0;
    if (i == 0) {
        int any_nonzero = 0;
        for (int k = 0; k < 64; k++)
            any_nonzero |= p[2 * k + 1];
        g_is64 = (any_nonzero == 0) ? 1 : 0;
    }
}

__global__ void convert_hist(const void* __restrict__ p)
{
    const int i = blockIdx.x * blockDim.x + threadIdx.x;
    if (i >= 2 * NE) return;
    int v;
    if (g_is64) v = (int)((const long long*)p)[i];
    else        v = ((const int*)p)[i];
    v = min(max(v, 0), NN - 1);
    g_idx[i] = v;
    if (i >= NE) atomicAdd(&g_deg[v], 1);
}

// ---------------------------------------------------------------------------
// Single-block exclusive scan: 1024 threads x 10 elements each.
// ---------------------------------------------------------------------------
__global__ void scan_deg_fast()
{
    const int t = threadIdx.x;
    const int lane = t & 31, warp = t >> 5;
    const int base = t * 10;

    int lexcl[10];
    int sum = 0;
#pragma unroll
    for (int i = 0; i < 10; i++) {
        const int idx = base + i;
        const int v = (idx < NN) ? __ldg(&g_deg[idx]) : 0;
        lexcl[i] = sum;
        sum += v;
    }

    int x = sum;
#pragma unroll
    for (int d = 1; d < 32; d <<= 1) {
        int y = __shfl_up_sync(0xffffffffu, x, d);
        if (lane >= d) x += y;
    }
    __shared__ int wsum[32];
    if (lane == 31) wsum[warp] = x;
    __syncthreads();
    if (warp == 0) {
        int w = wsum[lane];
#pragma unroll
        for (int d = 1; d < 32; d <<= 1) {
            int y = __shfl_up_sync(0xffffffffu, w, d);
            if (lane >= d) w += y;
        }
        wsum[lane] = w;
    }
    __syncthreads();

    const int texcl = (x - sum) + (warp ? wsum[warp - 1] : 0);
#pragma unroll
    for (int i = 0; i < 10; i++) {
        const int idx = base + i;
        if (idx < NN) {
            const int o = texcl + lexcl[i];
            g_off[idx] = o;
            g_cur[idx] = o;
        }
    }
    if (t == 1023) g_off[NN] = wsum[31];
}

__global__ void fill_csr()
{
    const int e = blockIdx.x * blockDim.x + threadIdx.x;
    if (e >= NE) return;
    const int dst = g_idx[NE + e];
    const int pos = atomicAdd(&g_cur[dst], 1);
    g_esrc[pos] = g_idx[e];
}

// ---------------------------------------------------------------------------
// 128x64 tiled SGEMM for N=K=256, 128 threads, 8x8 microtile, BK=16.
// Balanced 1.0 B-LDS/FMA; same-ty/tx lanes broadcast smem reads.
// Grid (4, 79) = 316 blocks.
// ---------------------------------------------------------------------------
template<bool RELU_IN>
__global__ void __launch_bounds__(128)
gemm128x64(const float* __restrict__ A, const float* __restrict__ B,
           const float* __restrict__ bias, float* __restrict__ C, int M)
{
    constexpr int KD = 256;
    constexpr int ND = 256;
    __shared__ float As[16][132];   // [k][m] transposed, padded stride
    __shared__ float Bs[16][64];    // [k][n]

    const int tid = threadIdx.x;
    const int ty = tid >> 3;        // 0..15 -> rows ty*8..+7 (128)
    const int tx = tid & 7;         // 0..7  -> cols tx*8..+7 (64)
    const int m0 = blockIdx.y * 128;
    const int n0 = blockIdx.x * 64;

    // A tile: 128x16 = 512 float4 -> 4/thread. B tile: 16x64 = 256 f4 -> 2/thread.
    const int a_r[4] = { (tid + 0) >> 2, (tid + 128) >> 2, (tid + 256) >> 2, (tid + 384) >> 2 };
    const int a_c[4] = { (tid + 0) & 3,  (tid + 128) & 3,  (tid + 256) & 3,  (tid + 384) & 3 };
    const int b_r[2] = { (tid + 0) >> 4, (tid + 128) >> 4 };
    const int b_c[2] = { (tid + 0) & 15, (tid + 128) & 15 };

    float acc[8][8];
#pragma unroll
    for (int i = 0; i < 8; i++)
#pragma unroll
        for (int j = 0; j < 8; j++) acc[i][j] = 0.f;

    const float4 z4 = make_float4(0.f, 0.f, 0.f, 0.f);
    float4 ra[4], rb[2];

#pragma unroll
    for (int i = 0; i < 4; i++)
        ra[i] = (m0 + a_r[i] < M)
            ? *reinterpret_cast<const float4*>(&A[(size_t)(m0 + a_r[i]) * KD + a_c[i] * 4]) : z4;
#pragma unroll
    for (int i = 0; i < 2; i++)
        rb[i] = *reinterpret_cast<const float4*>(&B[(size_t)b_r[i] * ND + n0 + b_c[i] * 4]);

    for (int k0 = 0; k0 < KD; k0 += 16) {
#pragma unroll
        for (int i = 0; i < 4; i++) {
            float4 v = ra[i];
            if (RELU_IN) {
                v.x = fmaxf(v.x, 0.f); v.y = fmaxf(v.y, 0.f);
                v.z = fmaxf(v.z, 0.f); v.w = fmaxf(v.w, 0.f);
            }
            As[a_c[i] * 4 + 0][a_r[i]] = v.x;
            As[a_c[i] * 4 + 1][a_r[i]] = v.y;
            As[a_c[i] * 4 + 2][a_r[i]] = v.z;
            As[a_c[i] * 4 + 3][a_r[i]] = v.w;
        }
#pragma unroll
        for (int i = 0; i < 2; i++)
            *reinterpret_cast<float4*>(&Bs[b_r[i]][b_c[i] * 4]) = rb[i];
        __syncthreads();

        if (k0 + 16 < KD) {
            const int kn = k0 + 16;
#pragma unroll
            for (int i = 0; i < 4; i++)
                ra[i] = (m0 + a_r[i] < M)
                    ? *reinterpret_cast<const float4*>(&A[(size_t)(m0 + a_r[i]) * KD + kn + a_c[i] * 4]) : z4;
#pragma unroll
            for (int i = 0; i < 2; i++)
                rb[i] = *reinterpret_cast<const float4*>(&B[(size_t)(kn + b_r[i]) * ND + n0 + b_c[i] * 4]);
        }

#pragma unroll
        for (int k = 0; k < 16; k++) {
            const float4 a0 = *reinterpret_cast<const float4*>(&As[k][ty * 8]);
            const float4 a1 = *reinterpret_cast<const float4*>(&As[k][ty * 8 + 4]);
            const float4 b0 = *reinterpret_cast<const float4*>(&Bs[k][tx * 8]);
            const float4 b1 = *reinterpret_cast<const float4*>(&Bs[k][tx * 8 + 4]);
            const float a[8] = {a0.x, a0.y, a0.z, a0.w, a1.x, a1.y, a1.z, a1.w};
            const float b[8] = {b0.x, b0.y, b0.z, b0.w, b1.x, b1.y, b1.z, b1.w};
#pragma unroll
            for (int i = 0; i < 8; i++)
#pragma unroll
                for (int j = 0; j < 8; j++)
                    acc[i][j] += a[i] * b[j];
        }
        __syncthreads();
    }

    const float4 bi0 = *reinterpret_cast<const float4*>(&bias[n0 + tx * 8]);
    const float4 bi1 = *reinterpret_cast<const float4*>(&bias[n0 + tx * 8 + 4]);
#pragma unroll
    for (int i = 0; i < 8; i++) {
        const int row = m0 + ty * 8 + i;
        if (row >= M) continue;
        float4 o0 = make_float4(acc[i][0] + bi0.x, acc[i][1] + bi0.y,
                                acc[i][2] + bi0.z, acc[i][3] + bi0.w);
        float4 o1 = make_float4(acc[i][4] + bi1.x, acc[i][5] + bi1.y,
                                acc[i][6] + bi1.z, acc[i][7] + bi1.w);
        *reinterpret_cast<float4*>(&C[(size_t)row * ND + n0 + tx * 8]) = o0;
        *reinterpret_cast<float4*>(&C[(size_t)row * ND + n0 + tx * 8 + 4]) = o1;
    }
}

// ---------------------------------------------------------------------------
// Tiled SGEMM 64x64 (layer 3, N=40): C = act(A) @ B + bias.
// ---------------------------------------------------------------------------
template<bool RELU_IN>
__global__ void gemm64(const float* __restrict__ A, const float* __restrict__ B,
                       const float* __restrict__ bias, float* __restrict__ C,
                       int M, int N, int K)
{
    __shared__ float As[16][64];
    __shared__ float Bs[16][64];
    const int tid = threadIdx.x;
    const int ty = tid >> 4, tx = tid & 15;
    const int m0 = blockIdx.y * 64;
    const int n0 = blockIdx.x * 64;

    float acc[4][4];
#pragma unroll
    for (int i = 0; i < 4; i++)
#pragma unroll
        for (int j = 0; j < 4; j++) acc[i][j] = 0.f;

    const int la = tid * 4;
    const int ar = la >> 4, ac = la & 15;
    const int br = la >> 6, bc = la & 63;
    const int grow = m0 + ar;
    const int gcol = n0 + bc;

    float4 va = make_float4(0.f, 0.f, 0.f, 0.f);
    if (grow < M)
        va = *reinterpret_cast<const float4*>(&A[(size_t)grow * K + ac]);
    float4 vb = make_float4(0.f, 0.f, 0.f, 0.f);
    if (gcol < N)
        vb = *reinterpret_cast<const float4*>(&B[(size_t)br * N + gcol]);

    for (int k0 = 0; k0 < K; k0 += 16) {
        float4 sa = va;
        if (RELU_IN) {
            sa.x = fmaxf(sa.x, 0.f); sa.y = fmaxf(sa.y, 0.f);
            sa.z = fmaxf(sa.z, 0.f); sa.w = fmaxf(sa.w, 0.f);
        }
        As[ac + 0][ar] = sa.x; As[ac + 1][ar] = sa.y;
        As[ac + 2][ar] = sa.z; As[ac + 3][ar] = sa.w;
        Bs[br][bc + 0] = vb.x; Bs[br][bc + 1] = vb.y;
        Bs[br][bc + 2] = vb.z; Bs[br][bc + 3] = vb.w;
        __syncthreads();

        if (k0 + 16 < K) {
            va = make_float4(0.f, 0.f, 0.f, 0.f);
            if (grow < M)
                va = *reinterpret_cast<const float4*>(&A[(size_t)grow * K + k0 + 16 + ac]);
            vb = make_float4(0.f, 0.f, 0.f, 0.f);
            if (gcol < N)
                vb = *reinterpret_cast<const float4*>(&B[(size_t)(k0 + 16 + br) * N + gcol]);
        }

#pragma unroll
        for (int k = 0; k < 16; k++) {
            const float4 a4 = *reinterpret_cast<const float4*>(&As[k][ty * 4]);
            const float4 b4 = *reinterpret_cast<const float4*>(&Bs[k][tx * 4]);
            const float a[4] = {a4.x, a4.y, a4.z, a4.w};
            const float b[4] = {b4.x, b4.y, b4.z, b4.w};
#pragma unroll
            for (int i = 0; i < 4; i++)
#pragma unroll
                for (int j = 0; j < 4; j++)
                    acc[i][j] += a[i] * b[j];
        }
        __syncthreads();
    }

#pragma unroll
    for (int i = 0; i < 4; i++) {
        int row = m0 + ty * 4 + i;
        if (row >= M) continue;
#pragma unroll
        for (int j = 0; j < 4; j++) {
            int col = n0 + tx * 4 + j;
            if (col < N)
                C[(size_t)row * N + col] = acc[i][j] + bias[col];
        }
    }
}

// ---------------------------------------------------------------------------
// Pull-mode aggregation, D=256, vectorized. No atomics.
// ---------------------------------------------------------------------------
__global__ void agg256v(const float4* __restrict__ h4, float4* __restrict__ out4)
{
    const int tid = threadIdx.x;
    const int node = blockIdx.x * 4 + (tid >> 6);
    const int f4 = tid & 63;
    if (node >= NN) return;
    const int beg = g_off[node], end = g_off[node + 1];

    float4 acc = make_float4(0.f, 0.f, 0.f, 0.f);
    int e = beg;
    for (; e + 4 <= end; e += 4) {
        const int s0 = g_esrc[e + 0], s1 = g_esrc[e + 1];
        const int s2 = g_esrc[e + 2], s3 = g_esrc[e + 3];
        const float4 v0 = h4[(size_t)s0 * 64 + f4];
        const float4 v1 = h4[(size_t)s1 * 64 + f4];
        const float4 v2 = h4[(size_t)s2 * 64 + f4];
        const float4 v3 = h4[(size_t)s3 * 64 + f4];
        acc.x += (v0.x + v1.x) + (v2.x + v3.x);
        acc.y += (v0.y + v1.y) + (v2.y + v3.y);
        acc.z += (v0.z + v1.z) + (v2.z + v3.z);
        acc.w += (v0.w + v1.w) + (v2.w + v3.w);
    }
    for (; e < end; e++) {
        const float4 v = h4[(size_t)g_esrc[e] * 64 + f4];
        acc.x += v.x; acc.y += v.y; acc.z += v.z; acc.w += v.w;
    }
    out4[(size_t)node * 64 + f4] = acc;
}

// ---------------------------------------------------------------------------
// Pull-mode aggregation, D=40 (+ReLU): 8 nodes per 320-thread block.
// ---------------------------------------------------------------------------
__global__ void agg40_relu(const float* __restrict__ h, float* __restrict__ out)
{
    const int tid = threadIdx.x;
    const int node = blockIdx.x * 8 + tid / NC;
    const int f = tid % NC;
    if (node >= NN) return;
    const int beg = g_off[node], end = g_off[node + 1];

    float acc = 0.f;
    int e = beg;
    for (; e + 4 <= end; e += 4) {
        const int s0 = g_esrc[e + 0], s1 = g_esrc[e + 1];
        const int s2 = g_esrc[e + 2], s3 = g_esrc[e + 3];
        const float v0 = h[(size_t)s0 * NC + f];
        const float v1 = h[(size_t)s1 * NC + f];
        const float v2 = h[(size_t)s2 * NC + f];
        const float v3 = h[(size_t)s3 * NC + f];
        acc += (v0 + v1) + (v2 + v3);
    }
    for (; e < end; e++)
        acc += h[(size_t)g_esrc[e] * NC + f];
    out[(size_t)node * NC + f] = fmaxf(acc, 0.f);
}

// ---------------------------------------------------------------------------
extern "C" void kernel_launch(void* const* d_in, const int* in_sizes, int n_in,
                              void* d_out, int out_size)
{
    const float* x  = (const float*)d_in[0];
    const void*  ei = d_in[1];
    const float* W1 = (const float*)d_in[2];
    const float* b1 = (const float*)d_in[3];
    const float* W2 = (const float*)d_in[4];
    const float* b2 = (const float*)d_in[5];
    const float* W3 = (const float*)d_in[6];
    const float* b3 = (const float*)d_in[7];
    float* out = (float*)d_out;

    float4 *bufA, *bufB;
    cudaGetSymbolAddress((void**)&bufA, g_bufA);
    cudaGetSymbolAddress((void**)&bufB, g_bufB);

    static cudaStream_t s_side = nullptr;
    static cudaEvent_t ev_fork = nullptr, ev_join = nullptr;
    if (s_side == nullptr) {
        cudaStreamCreateWithFlags(&s_side, cudaStreamNonBlocking);
        cudaEventCreateWithFlags(&ev_fork, cudaEventDisableTiming);
        cudaEventCreateWithFlags(&ev_join, cudaEventDisableTiming);
    }

    const dim3 gHid(DH / 64, (NN + 127) / 128);       // (4, 79) = 316 blocks
    const dim3 gCls((NC + 63) / 64, (NN + 63) / 64);  // (1, 157)

    // Fork: CSR build on side stream, layer-1 GEMM on main stream.
    cudaEventRecord(ev_fork, 0);
    cudaStreamWaitEvent(s_side, ev_fork, 0);

    detect_and_zero<<<(NN + 255) / 256, 256, 0, s_side>>>((const int*)ei);
    convert_hist<<<(2 * NE + 255) / 256, 256, 0, s_side>>>(ei);
    scan_deg_fast<<<1, 1024, 0, s_side>>>();
    fill_csr<<<(NE + 255) / 256, 256, 0, s_side>>>();
    cudaEventRecord(ev_join, s_side);

    // Layer 1 GEMM overlaps the CSR build.
    gemm128x64<false><<<gHid, 128>>>(x, W1, b1, (float*)bufB, NN);

    // Join: aggregation needs both GEMM1 output and the CSR.
    cudaStreamWaitEvent(0, ev_join, 0);
    agg256v<<<(NN + 3) / 4, 256>>>(bufB, bufA);

    // Layer 2
    gemm128x64<true><<<gHid, 128>>>((const float*)bufA, W2, b2, (float*)bufB, NN);
    agg256v<<<(NN + 3) / 4, 256>>>(bufB, bufA);

    // Layer 3
    gemm64<true><<<gCls, 256>>>((const float*)bufA, W3, b3, (float*)bufB, NN, NC, DH);
    agg40_relu<<<(NN + 7) / 8, 320>>>((const float*)bufB, out);
}

// round 17
// speedup vs baseline: 1.6015x; 1.1114x over previous
#include <cuda_runtime.h>
#include <cuda_fp16.h>

#define NN 10000
#define NE 320000
#define DH 256
#define NC 40

// Static scratch (allowed).
__device__ __align__(16) float4 g_bufA[NN * DH / 4];   // fp32 agg outputs
__device__ __align__(16) float4 g_bufB[NN * DH / 4];   // fp32 (layer-3 h)
__device__ __align__(16) uint2  g_hmsg[NN * DH / 4];   // fp16 messages (64 uint2/row)
__device__ int g_idx[2 * NE];      // [0,NE)=src, [NE,2NE)=dst (clean int32)
__device__ int g_deg[NN];
__device__ int g_off[NN + 1];
__device__ int g_cur[NN];
__device__ int g_esrc[NE];         // src ids grouped by dst (CSR payload)
__device__ int g_is64;

// ---------------------------------------------------------------------------
// Detect edge-index dtype (int64 vs int32) AND zero the degree histogram.
// ---------------------------------------------------------------------------
__global__ void detect_and_zero(const int* __restrict__ p)
{
    const int i = blockIdx.x * blockDim.x + threadIdx.x;
    if (i < NN) g_deg[i] = 0;
    if (i == 0) {
        int any_nonzero = 0;
        for (int k = 0; k < 64; k++)
            any_nonzero |= p[2 * k + 1];
        g_is64 = (any_nonzero == 0) ? 1 : 0;
    }
}

__global__ void convert_hist(const void* __restrict__ p)
{
    const int i = blockIdx.x * blockDim.x + threadIdx.x;
    if (i >= 2 * NE) return;
    int v;
    if (g_is64) v = (int)((const long long*)p)[i];
    else        v = ((const int*)p)[i];
    v = min(max(v, 0), NN - 1);
    g_idx[i] = v;
    if (i >= NE) atomicAdd(&g_deg[v], 1);
}

// ---------------------------------------------------------------------------
// Single-block exclusive scan: 1024 threads x 10 elements each.
// ---------------------------------------------------------------------------
__global__ void scan_deg_fast()
{
    const int t = threadIdx.x;
    const int lane = t & 31, warp = t >> 5;
    const int base = t * 10;

    int lexcl[10];
    int sum = 0;
#pragma unroll
    for (int i = 0; i < 10; i++) {
        const int idx = base + i;
        const int v = (idx < NN) ? __ldg(&g_deg[idx]) : 0;
        lexcl[i] = sum;
        sum += v;
    }

    int x = sum;
#pragma unroll
    for (int d = 1; d < 32; d <<= 1) {
        int y = __shfl_up_sync(0xffffffffu, x, d);
        if (lane >= d) x += y;
    }
    __shared__ int wsum[32];
    if (lane == 31) wsum[warp] = x;
    __syncthreads();
    if (warp == 0) {
        int w = wsum[lane];
#pragma unroll
        for (int d = 1; d < 32; d <<= 1) {
            int y = __shfl_up_sync(0xffffffffu, w, d);
            if (lane >= d) w += y;
        }
        wsum[lane] = w;
    }
    __syncthreads();

    const int texcl = (x - sum) + (warp ? wsum[warp - 1] : 0);
#pragma unroll
    for (int i = 0; i < 10; i++) {
        const int idx = base + i;
        if (idx < NN) {
            const int o = texcl + lexcl[i];
            g_off[idx] = o;
            g_cur[idx] = o;
        }
    }
    if (t == 1023) g_off[NN] = wsum[31];
}

__global__ void fill_csr()
{
    const int e = blockIdx.x * blockDim.x + threadIdx.x;
    if (e >= NE) return;
    const int dst = g_idx[NE + e];
    const int pos = atomicAdd(&g_cur[dst], 1);
    g_esrc[pos] = g_idx[e];
}

// ---------------------------------------------------------------------------
// 128x64 tiled SGEMM for N=K=256: h = act(A) @ B + bias, stored as fp16.
// 256 threads, 8x4 microtile, BK=16, register-prefetch pipeline.
// Epilogue converts to __half and writes 8 halves (16B) per row-fragment.
// ---------------------------------------------------------------------------
template<bool RELU_IN>
__global__ void gemm128x64h(const float* __restrict__ A, const float* __restrict__ B,
                            const float* __restrict__ bias, uint2* __restrict__ H,
                            int M)
{
    constexpr int KD = 256;
    constexpr int ND = 256;
    __shared__ float As[16][132];
    __shared__ float Bs[16][64];

    const int tid = threadIdx.x;
    const int ty = tid >> 4, tx = tid & 15;
    const int m0 = blockIdx.y * 128;
    const int n0 = blockIdx.x * 64;

    const int a_row0 = (tid + 0)   >> 2, a_c40 = (tid + 0)   & 3;
    const int a_row1 = (tid + 256) >> 2, a_c41 = (tid + 256) & 3;
    const int b_row  = tid >> 4,         b_c4  = tid & 15;

    float acc[8][4];
#pragma unroll
    for (int i = 0; i < 8; i++)
#pragma unroll
        for (int j = 0; j < 4; j++) acc[i][j] = 0.f;

    const float4 z4 = make_float4(0.f, 0.f, 0.f, 0.f);
    float4 ra0 = z4, ra1 = z4, rb;

    if (m0 + a_row0 < M)
        ra0 = *reinterpret_cast<const float4*>(&A[(size_t)(m0 + a_row0) * KD + a_c40 * 4]);
    if (m0 + a_row1 < M)
        ra1 = *reinterpret_cast<const float4*>(&A[(size_t)(m0 + a_row1) * KD + a_c41 * 4]);
    rb = *reinterpret_cast<const float4*>(&B[(size_t)b_row * ND + n0 + b_c4 * 4]);

    for (int k0 = 0; k0 < KD; k0 += 16) {
        float4 sa0 = ra0, sa1 = ra1;
        if (RELU_IN) {
            sa0.x = fmaxf(sa0.x, 0.f); sa0.y = fmaxf(sa0.y, 0.f);
            sa0.z = fmaxf(sa0.z, 0.f); sa0.w = fmaxf(sa0.w, 0.f);
            sa1.x = fmaxf(sa1.x, 0.f); sa1.y = fmaxf(sa1.y, 0.f);
            sa1.z = fmaxf(sa1.z, 0.f); sa1.w = fmaxf(sa1.w, 0.f);
        }
        As[a_c40 * 4 + 0][a_row0] = sa0.x; As[a_c40 * 4 + 1][a_row0] = sa0.y;
        As[a_c40 * 4 + 2][a_row0] = sa0.z; As[a_c40 * 4 + 3][a_row0] = sa0.w;
        As[a_c41 * 4 + 0][a_row1] = sa1.x; As[a_c41 * 4 + 1][a_row1] = sa1.y;
        As[a_c41 * 4 + 2][a_row1] = sa1.z; As[a_c41 * 4 + 3][a_row1] = sa1.w;
        *reinterpret_cast<float4*>(&Bs[b_row][b_c4 * 4]) = rb;
        __syncthreads();

        if (k0 + 16 < KD) {
            const int kn = k0 + 16;
            ra0 = z4; ra1 = z4;
            if (m0 + a_row0 < M)
                ra0 = *reinterpret_cast<const float4*>(&A[(size_t)(m0 + a_row0) * KD + kn + a_c40 * 4]);
            if (m0 + a_row1 < M)
                ra1 = *reinterpret_cast<const float4*>(&A[(size_t)(m0 + a_row1) * KD + kn + a_c41 * 4]);
            rb = *reinterpret_cast<const float4*>(&B[(size_t)(kn + b_row) * ND + n0 + b_c4 * 4]);
        }

#pragma unroll
        for (int k = 0; k < 16; k++) {
            const float4 a0 = *reinterpret_cast<const float4*>(&As[k][ty * 8]);
            const float4 a1 = *reinterpret_cast<const float4*>(&As[k][ty * 8 + 4]);
            const float4 b4 = *reinterpret_cast<const float4*>(&Bs[k][tx * 4]);
            const float a[8] = {a0.x, a0.y, a0.z, a0.w, a1.x, a1.y, a1.z, a1.w};
            const float b[4] = {b4.x, b4.y, b4.z, b4.w};
#pragma unroll
            for (int i = 0; i < 8; i++)
#pragma unroll
                for (int j = 0; j < 4; j++)
                    acc[i][j] += a[i] * b[j];
        }
        __syncthreads();
    }

    const float4 bi = *reinterpret_cast<const float4*>(&bias[n0 + tx * 4]);
    // uint2 index: row * 64 + (n0 + tx*4)/4
    const int h_col = (n0 >> 2) + tx;
#pragma unroll
    for (int i = 0; i < 8; i++) {
        const int row = m0 + ty * 8 + i;
        if (row >= M) continue;
        const __half2 p0 = __floats2half2_rn(acc[i][0] + bi.x, acc[i][1] + bi.y);
        const __half2 p1 = __floats2half2_rn(acc[i][2] + bi.z, acc[i][3] + bi.w);
        uint2 o;
        o.x = *reinterpret_cast<const unsigned int*>(&p0);
        o.y = *reinterpret_cast<const unsigned int*>(&p1);
        H[(size_t)row * 64 + h_col] = o;
    }
}

// ---------------------------------------------------------------------------
// Tiled SGEMM 64x64 (layer 3, N=40): C = act(A) @ B + bias. fp32 throughout.
// ---------------------------------------------------------------------------
template<bool RELU_IN>
__global__ void gemm64(const float* __restrict__ A, const float* __restrict__ B,
                       const float* __restrict__ bias, float* __restrict__ C,
                       int M, int N, int K)
{
    __shared__ float As[16][64];
    __shared__ float Bs[16][64];
    const int tid = threadIdx.x;
    const int ty = tid >> 4, tx = tid & 15;
    const int m0 = blockIdx.y * 64;
    const int n0 = blockIdx.x * 64;

    float acc[4][4];
#pragma unroll
    for (int i = 0; i < 4; i++)
#pragma unroll
        for (int j = 0; j < 4; j++) acc[i][j] = 0.f;

    const int la = tid * 4;
    const int ar = la >> 4, ac = la & 15;
    const int br = la >> 6, bc = la & 63;
    const int grow = m0 + ar;
    const int gcol = n0 + bc;

    float4 va = make_float4(0.f, 0.f, 0.f, 0.f);
    if (grow < M)
        va = *reinterpret_cast<const float4*>(&A[(size_t)grow * K + ac]);
    float4 vb = make_float4(0.f, 0.f, 0.f, 0.f);
    if (gcol < N)
        vb = *reinterpret_cast<const float4*>(&B[(size_t)br * N + gcol]);

    for (int k0 = 0; k0 < K; k0 += 16) {
        float4 sa = va;
        if (RELU_IN) {
            sa.x = fmaxf(sa.x, 0.f); sa.y = fmaxf(sa.y, 0.f);
            sa.z = fmaxf(sa.z, 0.f); sa.w = fmaxf(sa.w, 0.f);
        }
        As[ac + 0][ar] = sa.x; As[ac + 1][ar] = sa.y;
        As[ac + 2][ar] = sa.z; As[ac + 3][ar] = sa.w;
        Bs[br][bc + 0] = vb.x; Bs[br][bc + 1] = vb.y;
        Bs[br][bc + 2] = vb.z; Bs[br][bc + 3] = vb.w;
        __syncthreads();

        if (k0 + 16 < K) {
            va = make_float4(0.f, 0.f, 0.f, 0.f);
            if (grow < M)
                va = *reinterpret_cast<const float4*>(&A[(size_t)grow * K + k0 + 16 + ac]);
            vb = make_float4(0.f, 0.f, 0.f, 0.f);
            if (gcol < N)
                vb = *reinterpret_cast<const float4*>(&B[(size_t)(k0 + 16 + br) * N + gcol]);
        }

#pragma unroll
        for (int k = 0; k < 16; k++) {
            const float4 a4 = *reinterpret_cast<const float4*>(&As[k][ty * 4]);
            const float4 b4 = *reinterpret_cast<const float4*>(&Bs[k][tx * 4]);
            const float a[4] = {a4.x, a4.y, a4.z, a4.w};
            const float b[4] = {b4.x, b4.y, b4.z, b4.w};
#pragma unroll
            for (int i = 0; i < 4; i++)
#pragma unroll
                for (int j = 0; j < 4; j++)
                    acc[i][j] += a[i] * b[j];
        }
        __syncthreads();
    }

#pragma unroll
    for (int i = 0; i < 4; i++) {
        int row = m0 + ty * 4 + i;
        if (row >= M) continue;
#pragma unroll
        for (int j = 0; j < 4; j++) {
            int col = n0 + tx * 4 + j;
            if (col < N)
                C[(size_t)row * N + col] = acc[i][j] + bias[col];
        }
    }
}

// ---------------------------------------------------------------------------
// Pull-mode aggregation over fp16 messages, D=256: 4 nodes per 256-thread
// block, 64 threads per node, each thread owns 4 features (one uint2 = 4
// halves, LDG.64). fp32 accumulation, fp32 output. No atomics.
// ---------------------------------------------------------------------------
__global__ void agg256h(const uint2* __restrict__ h2v, float4* __restrict__ out4)
{
    const int tid = threadIdx.x;
    const int node = blockIdx.x * 4 + (tid >> 6);
    const int f4 = tid & 63;
    if (node >= NN) return;
    const int beg = g_off[node], end = g_off[node + 1];

    float4 acc = make_float4(0.f, 0.f, 0.f, 0.f);
    int e = beg;
    for (; e + 4 <= end; e += 4) {
        const int s0 = g_esrc[e + 0], s1 = g_esrc[e + 1];
        const int s2 = g_esrc[e + 2], s3 = g_esrc[e + 3];
        const uint2 u0 = h2v[(size_t)s0 * 64 + f4];
        const uint2 u1 = h2v[(size_t)s1 * 64 + f4];
        const uint2 u2 = h2v[(size_t)s2 * 64 + f4];
        const uint2 u3 = h2v[(size_t)s3 * 64 + f4];
        const float2 a0 = __half22float2(*reinterpret_cast<const __half2*>(&u0.x));
        const float2 b0 = __half22float2(*reinterpret_cast<const __half2*>(&u0.y));
        const float2 a1 = __half22float2(*reinterpret_cast<const __half2*>(&u1.x));
        const float2 b1 = __half22float2(*reinterpret_cast<const __half2*>(&u1.y));
        const float2 a2 = __half22float2(*reinterpret_cast<const __half2*>(&u2.x));
        const float2 b2 = __half22float2(*reinterpret_cast<const __half2*>(&u2.y));
        const float2 a3 = __half22float2(*reinterpret_cast<const __half2*>(&u3.x));
        const float2 b3 = __half22float2(*reinterpret_cast<const __half2*>(&u3.y));
        acc.x += (a0.x + a1.x) + (a2.x + a3.x);
        acc.y += (a0.y + a1.y) + (a2.y + a3.y);
        acc.z += (b0.x + b1.x) + (b2.x + b3.x);
        acc.w += (b0.y + b1.y) + (b2.y + b3.y);
    }
    for (; e < end; e++) {
        const uint2 u = h2v[(size_t)g_esrc[e] * 64 + f4];
        const float2 a = __half22float2(*reinterpret_cast<const __half2*>(&u.x));
        const float2 b = __half22float2(*reinterpret_cast<const __half2*>(&u.y));
        acc.x += a.x; acc.y += a.y; acc.z += b.x; acc.w += b.y;
    }
    out4[(size_t)node * 64 + f4] = acc;
}

// ---------------------------------------------------------------------------
// Pull-mode aggregation, D=40 (+ReLU): 8 nodes per 320-thread block. fp32.
// ---------------------------------------------------------------------------
__global__ void agg40_relu(const float* __restrict__ h, float* __restrict__ out)
{
    const int tid = threadIdx.x;
    const int node = blockIdx.x * 8 + tid / NC;
    const int f = tid % NC;
    if (node >= NN) return;
    const int beg = g_off[node], end = g_off[node + 1];

    float acc = 0.f;
    int e = beg;
    for (; e + 4 <= end; e += 4) {
        const int s0 = g_esrc[e + 0], s1 = g_esrc[e + 1];
        const int s2 = g_esrc[e + 2], s3 = g_esrc[e + 3];
        const float v0 = h[(size_t)s0 * NC + f];
        const float v1 = h[(size_t)s1 * NC + f];
        const float v2 = h[(size_t)s2 * NC + f];
        const float v3 = h[(size_t)s3 * NC + f];
        acc += (v0 + v1) + (v2 + v3);
    }
    for (; e < end; e++)
        acc += h[(size_t)g_esrc[e] * NC + f];
    out[(size_t)node * NC + f] = fmaxf(acc, 0.f);
}

// ---------------------------------------------------------------------------
extern "C" void kernel_launch(void* const* d_in, const int* in_sizes, int n_in,
                              void* d_out, int out_size)
{
    const float* x  = (const float*)d_in[0];
    const void*  ei = d_in[1];
    const float* W1 = (const float*)d_in[2];
    const float* b1 = (const float*)d_in[3];
    const float* W2 = (const float*)d_in[4];
    const float* b2 = (const float*)d_in[5];
    const float* W3 = (const float*)d_in[6];
    const float* b3 = (const float*)d_in[7];
    float* out = (float*)d_out;

    float4 *bufA, *bufB;
    uint2  *hmsg;
    cudaGetSymbolAddress((void**)&bufA, g_bufA);
    cudaGetSymbolAddress((void**)&bufB, g_bufB);
    cudaGetSymbolAddress((void**)&hmsg, g_hmsg);

    static cudaStream_t s_side = nullptr;
    static cudaEvent_t ev_fork = nullptr, ev_join = nullptr;
    if (s_side == nullptr) {
        cudaStreamCreateWithFlags(&s_side, cudaStreamNonBlocking);
        cudaEventCreateWithFlags(&ev_fork, cudaEventDisableTiming);
        cudaEventCreateWithFlags(&ev_join, cudaEventDisableTiming);
    }

    const dim3 gHid(DH / 64, (NN + 127) / 128);       // (4, 79) = 316 blocks
    const dim3 gCls((NC + 63) / 64, (NN + 63) / 64);  // (1, 157)

    // Fork: CSR build on side stream, layer-1 GEMM on main stream.
    cudaEventRecord(ev_fork, 0);
    cudaStreamWaitEvent(s_side, ev_fork, 0);

    detect_and_zero<<<(NN + 255) / 256, 256, 0, s_side>>>((const int*)ei);
    convert_hist<<<(2 * NE + 255) / 256, 256, 0, s_side>>>(ei);
    scan_deg_fast<<<1, 1024, 0, s_side>>>();
    fill_csr<<<(NE + 255) / 256, 256, 0, s_side>>>();
    cudaEventRecord(ev_join, s_side);

    // Layer 1 GEMM overlaps the CSR build; messages stored fp16.
    gemm128x64h<false><<<gHid, 256>>>(x, W1, b1, hmsg, NN);

    // Join: aggregation needs both GEMM1 output and the CSR.
    cudaStreamWaitEvent(0, ev_join, 0);
    agg256h<<<(NN + 3) / 4, 256>>>(hmsg, bufA);

    // Layer 2
    gemm128x64h<true><<<gHid, 256>>>((const float*)bufA, W2, b2, hmsg, NN);
    agg256h<<<(NN + 3) / 4, 256>>>(hmsg, bufA);

    // Layer 3 (fp32 end to end)
    gemm64<true><<<gCls, 256>>>((const float*)bufA, W3, b3, (float*)bufB, NN, NC, DH);
    agg40_relu<<<(NN + 7) / 8, 320>>>((const float*)bufB, out);
}